// round 1
// baseline (speedup 1.0000x reference)
#include <cuda_runtime.h>

#define NB 512
#define NC 184
#define NHIST 24
#define NPRED 24
#define NF 17
#define NHID 32
#define NROWS (NB*NC)          // 94208
#define INDIM (NHIST+NF)       // 41
#define SEQ (NHIST+NPRED)      // 48
#define BLOCK 128
#define NBLK (NROWS/BLOCK)     // 736 exactly

// ---------------- weight staging buffers (device globals, no allocs) ----------
__device__ float g_WIN[INDIM*NHID];      // [k][m] = W_in[m][k]
__device__ float g_WIH4[NHID*NHID*4];    // [j][k][g] = W_ih[(g*32+j)][k]
__device__ float g_WHH4[NHID*NHID*4];    // [j][k][g] = W_hh[(g*32+j)][k]
__device__ float g_BG[NHID*4];           // [j][g] = b_ih[g*32+j] + b_hh[g*32+j]
__device__ float g_BIN[NHID];
__device__ float g_WOUT[NHID];
__device__ float g_BOUT[1];

__global__ void prep_kernel(const float* __restrict__ Win,  const float* __restrict__ bin,
                            const float* __restrict__ Wih,  const float* __restrict__ Whh,
                            const float* __restrict__ bih,  const float* __restrict__ bhh,
                            const float* __restrict__ Wout, const float* __restrict__ bout)
{
    int i = blockIdx.x*blockDim.x + threadIdx.x;
    if (i < INDIM*NHID) {
        int k = i / NHID, m = i % NHID;
        g_WIN[k*NHID + m] = Win[m*INDIM + k];
    }
    if (i < NHID*NHID*4) {
        int j = i / (NHID*4);
        int rem = i % (NHID*4);
        int k = rem / 4, g = rem % 4;
        g_WIH4[i] = Wih[(g*NHID + j)*NHID + k];
        g_WHH4[i] = Whh[(g*NHID + j)*NHID + k];
    }
    if (i < NHID*4) {
        int j = i / 4, g = i % 4;
        g_BG[i] = bih[g*NHID + j] + bhh[g*NHID + j];
    }
    if (i < NHID) {
        g_BIN[i]  = bin[i];
        g_WOUT[i] = Wout[i];
    }
    if (i == 0) g_BOUT[0] = bout[0];
}

// ---------------- activations: exp-based, ~1e-7 accurate, MUFU-cheap ----------
__device__ __forceinline__ float fsigmoid(float v) {
    return __fdividef(1.0f, 1.0f + __expf(-v));
}
__device__ __forceinline__ float ftanh_(float v) {
    return __fdividef(2.0f, 1.0f + __expf(-2.0f*v)) - 1.0f;
}

// ---------------- main recurrent kernel --------------------------------------
__global__ void __launch_bounds__(BLOCK) lstm_kernel(
    const float* __restrict__ pm25,     // [B,24,184,1] (read flat: row r owns [r*24, r*24+24))
    const float* __restrict__ feature,  // [B,48,184,17]
    float* __restrict__ out)            // [B,24,184,1]
{
    __shared__ float  sWIN[INDIM*NHID];      //  5248 B
    __shared__ float4 sWIH[NHID*NHID];       // 16384 B
    __shared__ float4 sWHH[NHID*NHID];       // 16384 B
    __shared__ float4 sBG[NHID];             //   512 B
    __shared__ float  sBIN[NHID];
    __shared__ float  sWOUT[NHID];
    __shared__ float  sBOUT;

    const int tid = threadIdx.x;
    for (int i = tid; i < INDIM*NHID; i += BLOCK) sWIN[i] = g_WIN[i];
    {
        const float4* a = (const float4*)g_WIH4;
        const float4* b = (const float4*)g_WHH4;
        for (int i = tid; i < NHID*NHID; i += BLOCK) { sWIH[i] = a[i]; sWHH[i] = b[i]; }
        const float4* bg = (const float4*)g_BG;
        if (tid < NHID) {
            sBG[tid]  = bg[tid];
            sBIN[tid] = g_BIN[tid];
            sWOUT[tid]= g_WOUT[tid];
        }
        if (tid == 0) sBOUT = g_BOUT[0];
    }
    __syncthreads();

    const int r = blockIdx.x*BLOCK + tid;   // < 94208 exactly (grid = 736)
    const int b = r / NC;
    const int c = r - b*NC;

    // recurrent state in registers (all static indexing)
    float xn[NHIST];
    #pragma unroll
    for (int t = 0; t < NHIST; t++) xn[t] = pm25[(size_t)r*NHIST + t];

    float h[NHID], cc[NHID];
    #pragma unroll
    for (int m = 0; m < NHID; m++) { h[m] = 0.0f; cc[m] = 0.0f; }

    const float* fptr = feature + (((size_t)b*SEQ + NHIST)*NC + c)*NF;
    float* optr = out + (size_t)b*NPRED*NC + c;

    #pragma unroll 1
    for (int s = 0; s < NPRED; s++) {
        // ---- fetch this step's future features (17 floats) ----
        float feat[NF];
        #pragma unroll
        for (int f = 0; f < NF; f++) feat[f] = fptr[f];
        fptr += (size_t)NC*NF;

        // ---- x = concat(xn, feat) @ W_in^T + b_in : 41x32 ----
        float x[NHID];
        #pragma unroll
        for (int m = 0; m < NHID; m++) x[m] = sBIN[m];
        #pragma unroll
        for (int k = 0; k < NHIST; k++) {
            const float v = xn[k];
            #pragma unroll
            for (int m = 0; m < NHID; m++) x[m] = fmaf(sWIN[k*NHID + m], v, x[m]);
        }
        #pragma unroll
        for (int k = 0; k < NF; k++) {
            const float v = feat[k];
            #pragma unroll
            for (int m = 0; m < NHID; m++) x[m] = fmaf(sWIN[(NHIST+k)*NHID + m], v, x[m]);
        }

        // ---- gates + cell update + output accumulation ----
        float hn[NHID];
        float pred = sBOUT;
        #pragma unroll
        for (int j = 0; j < NHID; j++) {
            const float4 bg = sBG[j];
            float ai = bg.x, af = bg.y, ag = bg.z, ao = bg.w;
            #pragma unroll
            for (int k = 0; k < NHID; k++) {
                const float4 w = sWIH[j*NHID + k];
                const float v = x[k];
                ai = fmaf(w.x, v, ai);
                af = fmaf(w.y, v, af);
                ag = fmaf(w.z, v, ag);
                ao = fmaf(w.w, v, ao);
            }
            #pragma unroll
            for (int k = 0; k < NHID; k++) {
                const float4 w = sWHH[j*NHID + k];
                const float v = h[k];
                ai = fmaf(w.x, v, ai);
                af = fmaf(w.y, v, af);
                ag = fmaf(w.z, v, ag);
                ao = fmaf(w.w, v, ao);
            }
            const float ig = fsigmoid(ai);
            const float fg = fsigmoid(af);
            const float gg = ftanh_(ag);
            const float og = fsigmoid(ao);
            const float cj = fmaf(fg, cc[j], ig*gg);
            cc[j] = cj;
            const float hj = og * ftanh_(cj);
            hn[j] = hj;
            pred = fmaf(sWOUT[j], hj, pred);
        }
        #pragma unroll
        for (int m = 0; m < NHID; m++) h[m] = hn[m];

        // ---- emit prediction, shift history window ----
        optr[(size_t)s*NC] = pred;
        #pragma unroll
        for (int t = 0; t < NHIST-1; t++) xn[t] = xn[t+1];
        xn[NHIST-1] = pred;
    }
}

extern "C" void kernel_launch(void* const* d_in, const int* in_sizes, int n_in,
                              void* d_out, int out_size)
{
    const float* pm25    = (const float*)d_in[0];
    const float* feature = (const float*)d_in[1];
    // d_in[2] time_feature: unused by the model
    const float* Win  = (const float*)d_in[3];
    const float* bin  = (const float*)d_in[4];
    const float* Wih  = (const float*)d_in[5];
    const float* Whh  = (const float*)d_in[6];
    const float* bih  = (const float*)d_in[7];
    const float* bhh  = (const float*)d_in[8];
    const float* Wout = (const float*)d_in[9];
    const float* bout = (const float*)d_in[10];
    float* out = (float*)d_out;

    prep_kernel<<<16, 256>>>(Win, bin, Wih, Whh, bih, bhh, Wout, bout);
    lstm_kernel<<<NBLK, BLOCK>>>(pm25, feature, out);
}

// round 2
// speedup vs baseline: 1.0829x; 1.0829x over previous
#include <cuda_runtime.h>

#define NB 512
#define NC 184
#define NHIST 24
#define NPRED 24
#define NF 17
#define NHID 32
#define NROWS (NB*NC)          // 94208
#define INDIM (NHIST+NF)       // 41
#define SEQ (NHIST+NPRED)      // 48
#define WARPS 8
#define BLOCK (WARPS*32)       // 256
#define NBLK (NROWS/WARPS)     // 11776 exactly

typedef unsigned long long ull;

// ---------------- staged weight layouts (device globals) ----------------------
// Gate pair-K layout: [kk][m] float4 = { Wg0[m][2kk], Wg0[m][2kk+1], Wg1[m][2kk], Wg1[m][2kk+1] }
__device__ float4 g_IHA[16*NHID];   // gates i,f of W_ih
__device__ float4 g_IHB[16*NHID];   // gates g,o of W_ih
__device__ float4 g_HHA[16*NHID];   // gates i,f of W_hh
__device__ float4 g_HHB[16*NHID];   // gates g,o of W_hh
__device__ float2 g_WIN2[20*NHID];  // [kk][m] = { Win[m][2kk], Win[m][2kk+1] } for k<40
__device__ float  g_WINL[NHID];     // Win[m][40]
__device__ float4 g_BG4[NHID];      // per-m gate biases (b_ih + b_hh), order i,f,g,o
__device__ float  g_BIN[NHID];
__device__ float  g_WOUT[NHID];
__device__ float  g_BOUT[1];

__global__ void prep_kernel(const float* __restrict__ Win,  const float* __restrict__ bin,
                            const float* __restrict__ Wih,  const float* __restrict__ Whh,
                            const float* __restrict__ bih,  const float* __restrict__ bhh,
                            const float* __restrict__ Wout, const float* __restrict__ bout)
{
    int i = blockIdx.x*blockDim.x + threadIdx.x;
    if (i < 16*NHID) {
        int kk = i / NHID, m = i % NHID;
        int k0 = 2*kk, k1 = 2*kk+1;
        g_IHA[i] = make_float4(Wih[(0*NHID+m)*NHID+k0], Wih[(0*NHID+m)*NHID+k1],
                               Wih[(1*NHID+m)*NHID+k0], Wih[(1*NHID+m)*NHID+k1]);
        g_IHB[i] = make_float4(Wih[(2*NHID+m)*NHID+k0], Wih[(2*NHID+m)*NHID+k1],
                               Wih[(3*NHID+m)*NHID+k0], Wih[(3*NHID+m)*NHID+k1]);
        g_HHA[i] = make_float4(Whh[(0*NHID+m)*NHID+k0], Whh[(0*NHID+m)*NHID+k1],
                               Whh[(1*NHID+m)*NHID+k0], Whh[(1*NHID+m)*NHID+k1]);
        g_HHB[i] = make_float4(Whh[(2*NHID+m)*NHID+k0], Whh[(2*NHID+m)*NHID+k1],
                               Whh[(3*NHID+m)*NHID+k0], Whh[(3*NHID+m)*NHID+k1]);
    }
    if (i < 20*NHID) {
        int kk = i / NHID, m = i % NHID;
        g_WIN2[i] = make_float2(Win[m*INDIM + 2*kk], Win[m*INDIM + 2*kk+1]);
    }
    if (i < NHID) {
        g_WINL[i] = Win[i*INDIM + 40];
        g_BG4[i]  = make_float4(bih[0*NHID+i]+bhh[0*NHID+i], bih[1*NHID+i]+bhh[1*NHID+i],
                                bih[2*NHID+i]+bhh[2*NHID+i], bih[3*NHID+i]+bhh[3*NHID+i]);
        g_BIN[i]  = bin[i];
        g_WOUT[i] = Wout[i];
    }
    if (i == 0) g_BOUT[0] = bout[0];
}

// ---------------- f32x2 packed-FMA helpers (Blackwell) -------------------------
__device__ __forceinline__ ull pack2(float lo, float hi) {
    ull u; asm("mov.b64 %0, {%1,%2};" : "=l"(u) : "f"(lo), "f"(hi)); return u;
}
__device__ __forceinline__ float2 unpack2(ull u) {
    float2 f; asm("mov.b64 {%0,%1}, %2;" : "=f"(f.x), "=f"(f.y) : "l"(u)); return f;
}
__device__ __forceinline__ ull ffma2(ull a, ull b, ull c) {
    ull d; asm("fma.rn.f32x2 %0, %1, %2, %3;" : "=l"(d) : "l"(a), "l"(b), "l"(c)); return d;
}
__device__ __forceinline__ float hsum2(ull u) { float2 f = unpack2(u); return f.x + f.y; }

// ---------------- activations --------------------------------------------------
__device__ __forceinline__ float fsigmoid(float v) {
    return __fdividef(1.0f, 1.0f + __expf(-v));
}
__device__ __forceinline__ float ftanh_(float v) {
    return __fdividef(2.0f, 1.0f + __expf(-2.0f*v)) - 1.0f;
}

// ---------------- per-warp scratch --------------------------------------------
struct WarpBuf {
    float2 v[22];   // 44 floats: concat(xn[24], feat[17]) + pad
    float2 x[16];   // x[32]
    float2 h[16];   // h[32]
};

// ---------------- main kernel: one warp per row --------------------------------
__global__ void __launch_bounds__(BLOCK, 5) lstm_kernel(
    const float* __restrict__ pm25,     // raw-reinterpret: row r owns [r*24, r*24+24)
    const float* __restrict__ feature,  // [B,48,184,17]
    float* __restrict__ out)            // [B,24,184,1]
{
    __shared__ float4 sIHA[16*NHID], sIHB[16*NHID], sHHA[16*NHID], sHHB[16*NHID];
    __shared__ float2 sWIN2[20*NHID];
    __shared__ float  sWINL[NHID], sBIN[NHID], sWOUT[NHID];
    __shared__ float4 sBG[NHID];
    __shared__ float  sBOUT;
    __shared__ WarpBuf wb[WARPS];

    const int tid  = threadIdx.x;
    const int w    = tid >> 5;
    const int lane = tid & 31;

    for (int i = tid; i < 16*NHID; i += BLOCK) {
        sIHA[i] = g_IHA[i]; sIHB[i] = g_IHB[i];
        sHHA[i] = g_HHA[i]; sHHB[i] = g_HHB[i];
    }
    for (int i = tid; i < 20*NHID; i += BLOCK) sWIN2[i] = g_WIN2[i];
    if (tid < NHID) {
        sWINL[tid] = g_WINL[tid];
        sBIN[tid]  = g_BIN[tid];
        sWOUT[tid] = g_WOUT[tid];
        sBG[tid]   = g_BG4[tid];
    }
    if (tid == 0) sBOUT = g_BOUT[0];
    __syncthreads();

    const int r = blockIdx.x*WARPS + w;     // row id, < 94208
    const int b = r / NC;
    const int c = r - b*NC;

    // lane t<24 holds history value xn[t]; lane m holds h[m], c[m]
    float xn = (lane < NHIST) ? pm25[(size_t)r*NHIST + lane] : 0.0f;
    float hv = 0.0f, cv = 0.0f;
    ((float*)wb[w].h)[lane] = 0.0f;

    const float* fptr = feature + (((size_t)b*SEQ + NHIST)*NC + c)*NF;
    float* optr = out + (size_t)b*NPRED*NC + c;

    const ull*  vp  = (const ull*)wb[w].v;
    const ull*  xp  = (const ull*)wb[w].x;
    const ull*  hp  = (const ull*)wb[w].h;
    const ull*  win = (const ull*)sWIN2;
    const ulonglong2* iha = (const ulonglong2*)sIHA;
    const ulonglong2* ihb = (const ulonglong2*)sIHB;
    const ulonglong2* hha = (const ulonglong2*)sHHA;
    const ulonglong2* hhb = (const ulonglong2*)sHHB;

    const float binv  = sBIN[lane];
    const float winl  = sWINL[lane];
    const float woutv = sWOUT[lane];
    const float4 bg   = sBG[lane];

    #pragma unroll 1
    for (int s = 0; s < NPRED; s++) {
        // ---- stage concat(xn, feat) into per-warp smem ----
        float ft = (lane < NF) ? fptr[lane] : 0.0f;
        fptr += (size_t)NC*NF;
        if (lane < NHIST) ((float*)wb[w].v)[lane] = xn;
        if (lane < NF)    ((float*)wb[w].v)[NHIST + lane] = ft;
        float v40 = __shfl_sync(0xffffffffu, ft, 16);   // v[40] = feat[16]
        __syncwarp();

        // ---- x[m] = W_in[m,:41] . v + b_in  (paired-K f32x2) ----
        ull xacc = pack2(binv, 0.0f);
        #pragma unroll
        for (int kk = 0; kk < 20; kk++)
            xacc = ffma2(win[kk*NHID + lane], vp[kk], xacc);
        float xv = fmaf(winl, v40, hsum2(xacc));
        ((float*)wb[w].x)[lane] = xv;
        __syncwarp();

        // ---- gates (paired-K f32x2, 4 independent accumulators) ----
        ull ai = pack2(bg.x, 0.0f), af = pack2(bg.y, 0.0f);
        ull ag = pack2(bg.z, 0.0f), ao = pack2(bg.w, 0.0f);
        #pragma unroll
        for (int kk = 0; kk < 16; kk++) {
            const ull xk = xp[kk];
            const ulonglong2 wA = iha[kk*NHID + lane];
            const ulonglong2 wB = ihb[kk*NHID + lane];
            ai = ffma2(wA.x, xk, ai);
            af = ffma2(wA.y, xk, af);
            ag = ffma2(wB.x, xk, ag);
            ao = ffma2(wB.y, xk, ao);
        }
        #pragma unroll
        for (int kk = 0; kk < 16; kk++) {
            const ull hk = hp[kk];
            const ulonglong2 wA = hha[kk*NHID + lane];
            const ulonglong2 wB = hhb[kk*NHID + lane];
            ai = ffma2(wA.x, hk, ai);
            af = ffma2(wA.y, hk, af);
            ag = ffma2(wB.x, hk, ag);
            ao = ffma2(wB.y, hk, ao);
        }

        const float ig = fsigmoid(hsum2(ai));
        const float fg = fsigmoid(hsum2(af));
        const float gg = ftanh_ (hsum2(ag));
        const float og = fsigmoid(hsum2(ao));
        cv = fmaf(fg, cv, ig*gg);
        hv = og * ftanh_(cv);
        __syncwarp();                      // everyone done reading old h
        ((float*)wb[w].h)[lane] = hv;      // publish new h (read next step)

        // ---- pred = W_out . h + b_out (butterfly reduce) ----
        float p = hv * woutv;
        #pragma unroll
        for (int d = 16; d >= 1; d >>= 1)
            p += __shfl_xor_sync(0xffffffffu, p, d);
        p += sBOUT;
        if (lane == 0) optr[(size_t)s*NC] = p;

        // ---- shift history window ----
        float xs = __shfl_down_sync(0xffffffffu, xn, 1);
        xn = (lane == NHIST-1) ? p : xs;
    }
}

extern "C" void kernel_launch(void* const* d_in, const int* in_sizes, int n_in,
                              void* d_out, int out_size)
{
    const float* pm25    = (const float*)d_in[0];
    const float* feature = (const float*)d_in[1];
    // d_in[2] time_feature: unused by the model
    const float* Win  = (const float*)d_in[3];
    const float* bin  = (const float*)d_in[4];
    const float* Wih  = (const float*)d_in[5];
    const float* Whh  = (const float*)d_in[6];
    const float* bih  = (const float*)d_in[7];
    const float* bhh  = (const float*)d_in[8];
    const float* Wout = (const float*)d_in[9];
    const float* bout = (const float*)d_in[10];
    float* out = (float*)d_out;

    prep_kernel<<<3, 256>>>(Win, bin, Wih, Whh, bih, bhh, Wout, bout);
    lstm_kernel<<<NBLK, BLOCK>>>(pm25, feature, out);
}

// round 3
// speedup vs baseline: 2.6711x; 2.4665x over previous
#include <cuda_runtime.h>

#define NB 512
#define NC 184
#define NHIST 24
#define NPRED 24
#define NF 17
#define NHID 32
#define NROWS (NB*NC)          // 94208
#define INDIM 41
#define SEQ 48
#define R 4
#define WARPS 8
#define BLOCK 256
#define ROWS_PER_BLK (WARPS*R)      // 32
#define NBLK (NROWS/ROWS_PER_BLK)   // 2944 exactly

typedef unsigned long long ull;

// ---------------- staged weight layouts (device globals) ----------------------
// Gate pair-K layout: [kk][m] float4 = { Wg0[m][2kk], Wg0[m][2kk+1], Wg1[m][2kk], Wg1[m][2kk+1] }
__device__ float4 g_IHA[16*NHID];   // gates i,f of W_ih
__device__ float4 g_IHB[16*NHID];   // gates g,o of W_ih
__device__ float4 g_HHA[16*NHID];   // gates i,f of W_hh
__device__ float4 g_HHB[16*NHID];   // gates g,o of W_hh
__device__ float4 g_WINP[10*NHID];  // [kk2][m] = Win[m][4kk2 .. 4kk2+3]
__device__ float  g_WINL[NHID];     // Win[m][40]
__device__ float4 g_BG4[NHID];      // gate biases (b_ih+b_hh), order i,f,g,o
__device__ float  g_BIN[NHID];
__device__ float  g_WOUT[NHID];
__device__ float  g_BOUT[1];

__global__ void prep_kernel(const float* __restrict__ Win,  const float* __restrict__ bin,
                            const float* __restrict__ Wih,  const float* __restrict__ Whh,
                            const float* __restrict__ bih,  const float* __restrict__ bhh,
                            const float* __restrict__ Wout, const float* __restrict__ bout)
{
    int i = blockIdx.x*blockDim.x + threadIdx.x;
    if (i < 16*NHID) {
        int kk = i / NHID, m = i % NHID;
        int k0 = 2*kk, k1 = 2*kk+1;
        g_IHA[i] = make_float4(Wih[(0*NHID+m)*NHID+k0], Wih[(0*NHID+m)*NHID+k1],
                               Wih[(1*NHID+m)*NHID+k0], Wih[(1*NHID+m)*NHID+k1]);
        g_IHB[i] = make_float4(Wih[(2*NHID+m)*NHID+k0], Wih[(2*NHID+m)*NHID+k1],
                               Wih[(3*NHID+m)*NHID+k0], Wih[(3*NHID+m)*NHID+k1]);
        g_HHA[i] = make_float4(Whh[(0*NHID+m)*NHID+k0], Whh[(0*NHID+m)*NHID+k1],
                               Whh[(1*NHID+m)*NHID+k0], Whh[(1*NHID+m)*NHID+k1]);
        g_HHB[i] = make_float4(Whh[(2*NHID+m)*NHID+k0], Whh[(2*NHID+m)*NHID+k1],
                               Whh[(3*NHID+m)*NHID+k0], Whh[(3*NHID+m)*NHID+k1]);
    }
    if (i < 10*NHID) {
        int kk2 = i / NHID, m = i % NHID;
        g_WINP[i] = make_float4(Win[m*INDIM + 4*kk2+0], Win[m*INDIM + 4*kk2+1],
                                Win[m*INDIM + 4*kk2+2], Win[m*INDIM + 4*kk2+3]);
    }
    if (i < NHID) {
        g_WINL[i] = Win[i*INDIM + 40];
        g_BG4[i]  = make_float4(bih[0*NHID+i]+bhh[0*NHID+i], bih[1*NHID+i]+bhh[1*NHID+i],
                                bih[2*NHID+i]+bhh[2*NHID+i], bih[3*NHID+i]+bhh[3*NHID+i]);
        g_BIN[i]  = bin[i];
        g_WOUT[i] = Wout[i];
    }
    if (i == 0) g_BOUT[0] = bout[0];
}

// ---------------- f32x2 packed-FMA helpers (Blackwell) -------------------------
__device__ __forceinline__ ull pack2(float lo, float hi) {
    ull u; asm("mov.b64 %0, {%1,%2};" : "=l"(u) : "f"(lo), "f"(hi)); return u;
}
__device__ __forceinline__ ull ffma2(ull a, ull b, ull c) {
    ull d; asm("fma.rn.f32x2 %0, %1, %2, %3;" : "=l"(d) : "l"(a), "l"(b), "l"(c)); return d;
}
__device__ __forceinline__ float hsum2(ull u) {
    float lo, hi; asm("mov.b64 {%0,%1}, %2;" : "=f"(lo), "=f"(hi) : "l"(u));
    return lo + hi;
}

// ---------------- activations --------------------------------------------------
__device__ __forceinline__ float fsigmoid(float v) {
    return __fdividef(1.0f, 1.0f + __expf(-v));
}
__device__ __forceinline__ float ftanh_(float v) {
    return __fdividef(2.0f, 1.0f + __expf(-2.0f*v)) - 1.0f;
}

// ---------------- per-row smem buffer (x overlays v[0..31]) --------------------
struct __align__(16) RowBuf {
    float vx[44];   // step input v[41] (+pad); later overwritten by x[32]
    float h[32];
};  // 304 B

// ---------------- main kernel: one warp per 4 rows ------------------------------
__global__ void __launch_bounds__(BLOCK, 2) lstm_kernel(
    const float* __restrict__ pm25,     // raw reinterpret: row r owns [r*24, r*24+24)
    const float* __restrict__ feature,  // [B,48,184,17]
    float* __restrict__ out)            // [B,24,184,1]
{
    __shared__ float4 sIHA[16*NHID], sIHB[16*NHID], sHHA[16*NHID], sHHB[16*NHID]; // 32 KB
    __shared__ float4 sWINP[10*NHID];                                            // 5 KB
    __shared__ float  sWINL[NHID], sBIN[NHID], sWOUT[NHID];
    __shared__ float4 sBG[NHID];
    __shared__ float  sBOUT;
    __shared__ RowBuf rb[WARPS][R];                                              // 9.5 KB

    const int tid  = threadIdx.x;
    const int w    = tid >> 5;
    const int lane = tid & 31;

    #pragma unroll
    for (int i = tid; i < 16*NHID; i += BLOCK) {
        sIHA[i] = g_IHA[i]; sIHB[i] = g_IHB[i];
        sHHA[i] = g_HHA[i]; sHHB[i] = g_HHB[i];
    }
    for (int i = tid; i < 10*NHID; i += BLOCK) sWINP[i] = g_WINP[i];
    if (tid < NHID) {
        sWINL[tid] = g_WINL[tid];
        sBIN[tid]  = g_BIN[tid];
        sWOUT[tid] = g_WOUT[tid];
        sBG[tid]   = g_BG4[tid];
    }
    if (tid == 0) sBOUT = g_BOUT[0];

    const int r0 = (blockIdx.x*WARPS + w) * R;   // 4 consecutive rows, same b
    const int b  = r0 / NC;
    const int c0 = r0 - b*NC;

    float xn[R], cv[R];
    #pragma unroll
    for (int j = 0; j < R; j++) {
        xn[j] = (lane < NHIST) ? pm25[(size_t)(r0+j)*NHIST + lane] : 0.0f;
        cv[j] = 0.0f;
        rb[w][j].h[lane] = 0.0f;
    }

    const float* fptr = feature + (((size_t)b*SEQ + NHIST)*NC + c0)*NF;
    float* obase = out + (size_t)b*NPRED*NC + c0;

    __syncthreads();

    const ulonglong2* iha  = (const ulonglong2*)sIHA;
    const ulonglong2* ihb  = (const ulonglong2*)sIHB;
    const ulonglong2* hha  = (const ulonglong2*)sHHA;
    const ulonglong2* hhb  = (const ulonglong2*)sHHB;
    const ulonglong2* winp = (const ulonglong2*)sWINP;

    const float binv  = sBIN[lane];
    const float winl  = sWINL[lane];
    const float woutv = sWOUT[lane];
    const float4 bg   = sBG[lane];
    const float boutv = sBOUT;

    #pragma unroll 1
    for (int s = 0; s < NPRED; s++) {
        // ---- stage concat(xn, feat) for each row ----
        float ft[R], v40[R];
        #pragma unroll
        for (int j = 0; j < R; j++) ft[j] = (lane < NF) ? fptr[j*NF + lane] : 0.0f;
        fptr += (size_t)NC*NF;
        #pragma unroll
        for (int j = 0; j < R; j++) {
            if (lane < NHIST) rb[w][j].vx[lane] = xn[j];
            if (lane < NF)    rb[w][j].vx[NHIST + lane] = ft[j];
            v40[j] = __shfl_sync(0xffffffffu, ft[j], 16);
        }
        __syncwarp();

        // ---- x[m] = W_in[m,:41] . v + b_in (4 rows, shared weight loads) ----
        ull xacc[R];
        #pragma unroll
        for (int j = 0; j < R; j++) xacc[j] = pack2(binv, 0.0f);
        #pragma unroll
        for (int kk2 = 0; kk2 < 10; kk2++) {
            const ulonglong2 wp = winp[kk2*NHID + lane];
            #pragma unroll
            for (int j = 0; j < R; j++) {
                const ulonglong2 vv = ((const ulonglong2*)rb[w][j].vx)[kk2];
                xacc[j] = ffma2(wp.x, vv.x, xacc[j]);
                xacc[j] = ffma2(wp.y, vv.y, xacc[j]);
            }
        }
        float xv[R];
        #pragma unroll
        for (int j = 0; j < R; j++) xv[j] = fmaf(winl, v40[j], hsum2(xacc[j]));
        __syncwarp();                  // all lanes done reading v before x overlays it
        #pragma unroll
        for (int j = 0; j < R; j++) rb[w][j].vx[lane] = xv[j];
        __syncwarp();

        // ---- gates (shared weight loads feed 4 rows x 4 gates) ----
        ull ai[R], af[R], ag[R], ao[R];
        #pragma unroll
        for (int j = 0; j < R; j++) {
            ai[j] = pack2(bg.x, 0.0f); af[j] = pack2(bg.y, 0.0f);
            ag[j] = pack2(bg.z, 0.0f); ao[j] = pack2(bg.w, 0.0f);
        }
        #pragma unroll
        for (int kk2 = 0; kk2 < 8; kk2++) {
            const ulonglong2 a0 = iha[(2*kk2+0)*NHID + lane];
            const ulonglong2 b0 = ihb[(2*kk2+0)*NHID + lane];
            const ulonglong2 a1 = iha[(2*kk2+1)*NHID + lane];
            const ulonglong2 b1 = ihb[(2*kk2+1)*NHID + lane];
            #pragma unroll
            for (int j = 0; j < R; j++) {
                const ulonglong2 xk = ((const ulonglong2*)rb[w][j].vx)[kk2];
                ai[j] = ffma2(a0.x, xk.x, ai[j]);
                af[j] = ffma2(a0.y, xk.x, af[j]);
                ag[j] = ffma2(b0.x, xk.x, ag[j]);
                ao[j] = ffma2(b0.y, xk.x, ao[j]);
                ai[j] = ffma2(a1.x, xk.y, ai[j]);
                af[j] = ffma2(a1.y, xk.y, af[j]);
                ag[j] = ffma2(b1.x, xk.y, ag[j]);
                ao[j] = ffma2(b1.y, xk.y, ao[j]);
            }
        }
        #pragma unroll
        for (int kk2 = 0; kk2 < 8; kk2++) {
            const ulonglong2 a0 = hha[(2*kk2+0)*NHID + lane];
            const ulonglong2 b0 = hhb[(2*kk2+0)*NHID + lane];
            const ulonglong2 a1 = hha[(2*kk2+1)*NHID + lane];
            const ulonglong2 b1 = hhb[(2*kk2+1)*NHID + lane];
            #pragma unroll
            for (int j = 0; j < R; j++) {
                const ulonglong2 hk = ((const ulonglong2*)rb[w][j].h)[kk2];
                ai[j] = ffma2(a0.x, hk.x, ai[j]);
                af[j] = ffma2(a0.y, hk.x, af[j]);
                ag[j] = ffma2(b0.x, hk.x, ag[j]);
                ao[j] = ffma2(b0.y, hk.x, ao[j]);
                ai[j] = ffma2(a1.x, hk.y, ai[j]);
                af[j] = ffma2(a1.y, hk.y, af[j]);
                ag[j] = ffma2(b1.x, hk.y, ag[j]);
                ao[j] = ffma2(b1.y, hk.y, ao[j]);
            }
        }

        // ---- activations + cell update ----
        float hv[R];
        #pragma unroll
        for (int j = 0; j < R; j++) {
            const float ig = fsigmoid(hsum2(ai[j]));
            const float fg = fsigmoid(hsum2(af[j]));
            const float gg = ftanh_ (hsum2(ag[j]));
            const float og = fsigmoid(hsum2(ao[j]));
            cv[j] = fmaf(fg, cv[j], ig*gg);
            hv[j] = og * ftanh_(cv[j]);
        }
        __syncwarp();                  // all lanes done reading old h
        #pragma unroll
        for (int j = 0; j < R; j++) rb[w][j].h[lane] = hv[j];

        // ---- pred = W_out . h + b_out (butterfly; all lanes get result) ----
        float p[R];
        #pragma unroll
        for (int j = 0; j < R; j++) {
            float q = hv[j] * woutv;
            #pragma unroll
            for (int d = 16; d >= 1; d >>= 1)
                q += __shfl_xor_sync(0xffffffffu, q, d);
            p[j] = q + boutv;
        }
        if (lane == 0) {
            #pragma unroll
            for (int j = 0; j < R; j++) obase[(size_t)s*NC + j] = p[j];
        }

        // ---- shift history windows ----
        #pragma unroll
        for (int j = 0; j < R; j++) {
            const float xs = __shfl_down_sync(0xffffffffu, xn[j], 1);
            xn[j] = (lane == NHIST-1) ? p[j] : xs;
        }
    }
}

extern "C" void kernel_launch(void* const* d_in, const int* in_sizes, int n_in,
                              void* d_out, int out_size)
{
    const float* pm25    = (const float*)d_in[0];
    const float* feature = (const float*)d_in[1];
    // d_in[2] time_feature: unused by the model
    const float* Win  = (const float*)d_in[3];
    const float* bin  = (const float*)d_in[4];
    const float* Wih  = (const float*)d_in[5];
    const float* Whh  = (const float*)d_in[6];
    const float* bih  = (const float*)d_in[7];
    const float* bhh  = (const float*)d_in[8];
    const float* Wout = (const float*)d_in[9];
    const float* bout = (const float*)d_in[10];
    float* out = (float*)d_out;

    prep_kernel<<<3, 256>>>(Win, bin, Wih, Whh, bih, bhh, Wout, bout);
    lstm_kernel<<<NBLK, BLOCK>>>(pm25, feature, out);
}

// round 7
// speedup vs baseline: 6.3212x; 2.3666x over previous
#include <cuda_runtime.h>
#include <cuda_fp16.h>
#include <cstdint>

typedef unsigned int uint;

#define NC 184
#define NHIST 24
#define NPRED 24
#define NF 17
#define NHID 32
#define NROWS 94208
#define SEQ 48
#define GRID 736
#define NGATE 128

// dynamic smem layout (bytes)
#define SM_BHI  0        // B fp16 tile: [kc][n] 16B rows, 10*2048
#define SM_AHI  20480    // A hi: [kc][row] 16B rows
#define SM_ALO  40960    // A lo
#define SM_HBUF 61440    // h fp32 [128][33]
#define SM_WOUT 78336
#define SM_BOUT 78464
#define SM_SIZE 78592

// ---------------- device-global staged weights --------------------------------
__device__ __half g_B[10240];        // fused B tile, fp16, ldmatrix layout
__device__ float  g_Wf[NGATE*41];    // Wih@Win, n-ordered (n = 4j+g)
__device__ float  g_BG[NGATE];       // fused bias
__device__ float  g_WOUT[NHID];
__device__ float  g_BOUT[1];

__global__ void prep1(const float* __restrict__ Win, const float* __restrict__ bin,
                      const float* __restrict__ Wih, const float* __restrict__ bih,
                      const float* __restrict__ bhh,
                      const float* __restrict__ Wout, const float* __restrict__ bout)
{
    int idx = blockIdx.x*blockDim.x + threadIdx.x;
    if (idx < NGATE*41) {
        int n = idx / 41, k = idx % 41;
        int j = n >> 2, g = n & 3;
        int row = g*NHID + j;
        float s = 0.f;
        for (int m = 0; m < NHID; m++) s += Wih[row*NHID + m] * Win[m*41 + k];
        g_Wf[idx] = s;
    }
    if (idx < NGATE) {
        int j = idx >> 2, g = idx & 3;
        int row = g*NHID + j;
        float s = bih[row] + bhh[row];
        for (int m = 0; m < NHID; m++) s += Wih[row*NHID + m] * bin[m];
        g_BG[idx] = s;
    }
    if (idx < NHID) g_WOUT[idx] = Wout[idx];
    if (idx == 0) g_BOUT[0] = bout[0];
}

// B[k][n]: k<41 fused W; k=41 bias; 42..47 zero; 48..79 Whh. Stored [kc][n][k%8] fp16.
__global__ void prep2(const float* __restrict__ Whh)
{
    int idx = blockIdx.x*blockDim.x + threadIdx.x;
    if (idx >= NGATE*80) return;
    int n = idx / 80, k = idx % 80;
    int j = n >> 2, g = n & 3;
    float v = 0.f;
    if (k < 41)       v = g_Wf[n*41 + k];
    else if (k == 41) v = g_BG[n];
    else if (k >= 48) v = Whh[(g*NHID + j)*NHID + (k - 48)];
    g_B[(k >> 3)*1024 + n*8 + (k & 7)] = __float2half_rn(v);
}

// ---------------- PTX helpers ---------------------------------------------------
__device__ __forceinline__ uint smem_u32(const void* p) {
    uint a; asm("{ .reg .u64 t; cvta.to.shared.u64 t, %1; cvt.u32.u64 %0, t; }"
                : "=r"(a) : "l"(p));
    return a;
}

#define LDSM4(r0, r1, r2, r3, addr) \
    asm volatile("ldmatrix.sync.aligned.m8n8.x4.shared.b16 {%0,%1,%2,%3}, [%4];" \
        : "=r"(r0), "=r"(r1), "=r"(r2), "=r"(r3) : "r"(addr))

#define LDSM2(r0, r1, addr) \
    asm volatile("ldmatrix.sync.aligned.m8n8.x2.shared.b16 {%0,%1}, [%2];" \
        : "=r"(r0), "=r"(r1) : "r"(addr))

#define MMA16816(d, a, b) \
    asm volatile("mma.sync.aligned.m16n8k16.row.col.f32.f16.f16.f32 " \
        "{%0,%1,%2,%3}, {%4,%5,%6,%7}, {%8,%9}, {%0,%1,%2,%3};" \
        : "+f"((d)[0]), "+f"((d)[1]), "+f"((d)[2]), "+f"((d)[3]) \
        : "r"((a)[0]), "r"((a)[1]), "r"((a)[2]), "r"((a)[3]), \
          "r"((b)[0]), "r"((b)[1]))

// fp32 pair -> fp16x2 hi + fp16x2 lo (a in low half)
__device__ __forceinline__ void packpair(float a, float b, uint& hi, uint& lo) {
    __half2 h2 = __floats2half2_rn(a, b);
    hi = *reinterpret_cast<uint*>(&h2);
    float2 r = __half22float2(h2);
    __half2 l2 = __floats2half2_rn(a - r.x, b - r.y);
    lo = *reinterpret_cast<uint*>(&l2);
}

__device__ __forceinline__ float fsigmoid(float v) {
    return __fdividef(1.0f, 1.0f + __expf(-v));
}
__device__ __forceinline__ float ftanh_(float v) {
    return __fdividef(2.0f, 1.0f + __expf(-2.0f*v)) - 1.0f;
}

// ---------------- main kernel: HMMA LSTM ---------------------------------------
__global__ void __launch_bounds__(128) lstm_hmma_kernel(
    const float* __restrict__ pm25,
    const float* __restrict__ feature,
    float* __restrict__ out)
{
    extern __shared__ char smem[];
    const uint sb = smem_u32(smem);
    const int tid = threadIdx.x;
    const int w = tid >> 5, lane = tid & 31;

    // stage B + vectors
    {
        const uint4* s = (const uint4*)g_B;
        uint4* d = (uint4*)(smem + SM_BHI);
        #pragma unroll
        for (int i = 0; i < 10; i++) d[i*128 + tid] = s[i*128 + tid];
    }
    if (tid < NHID) ((float*)(smem + SM_WOUT))[tid] = g_WOUT[tid];
    if (tid == 0)   *(float*)(smem + SM_BOUT) = g_BOUT[0];
    {
        uint4 z = make_uint4(0,0,0,0);
        #pragma unroll
        for (int kc = 6; kc < 10; kc++) {
            ((uint4*)(smem + SM_AHI))[kc*128 + tid] = z;   // h=0
            ((uint4*)(smem + SM_ALO))[kc*128 + tid] = z;
        }
    }
    __syncthreads();

    // per-thread row state
    const int r = blockIdx.x*128 + tid;
    const int b = r / NC;
    const int c = r - b*NC;

    float xn[NHIST];
    #pragma unroll
    for (int t = 0; t < NHIST; t++) xn[t] = pm25[(size_t)r*NHIST + t];
    float cst[32];
    #pragma unroll
    for (int i = 0; i < 32; i++) cst[i] = 0.0f;

    const float* fptr = feature + (((size_t)b*SEQ + NHIST)*NC + c)*NF;
    float* optr = out + ((size_t)b*NPRED)*NC + c;

    const float* sW  = (const float*)(smem + SM_WOUT);
    const float boutv = *(const float*)(smem + SM_BOUT);
    float* hbuf = (float*)(smem + SM_HBUF);

    // ldmatrix lane base addresses
    const uint rowA   = (uint)(w<<5) + (lane & 7) + (((lane >> 3) & 1) << 3);
    const uint aHiB   = sb + SM_AHI + rowA*16 + ((uint)(lane >> 4) & 1)*2048;
    const uint aLoB   = sb + SM_ALO + rowA*16 + ((uint)(lane >> 4) & 1)*2048;
    const uint bBase  = sb + SM_BHI + (uint)(lane & 7)*16 + (((uint)(lane >> 3) & 1))*2048;

    #pragma unroll 1
    for (int s = 0; s < NPRED; s++) {
        // ---- build v = [xn | feat | 1(bias) | 0pad], split fp16 hi/lo ----
        float ft[NF];
        #pragma unroll
        for (int f = 0; f < NF; f++) ft[f] = fptr[f];
        fptr += (size_t)NC*NF;

        uint vh[24], vl[24];
        #pragma unroll
        for (int p = 0; p < 12; p++) packpair(xn[2*p], xn[2*p+1], vh[p], vl[p]);
        #pragma unroll
        for (int p = 0; p < 8; p++) packpair(ft[2*p], ft[2*p+1], vh[12+p], vl[12+p]);
        packpair(ft[16], 1.0f, vh[20], vl[20]);        // k40 = feat16, k41 = 1.0 (bias col)
        vh[21] = vh[22] = vh[23] = 0u;
        vl[21] = vl[22] = vl[23] = 0u;

        #pragma unroll
        for (int kc = 0; kc < 6; kc++) {
            ((uint4*)(smem + SM_AHI))[kc*128 + tid] =
                make_uint4(vh[4*kc], vh[4*kc+1], vh[4*kc+2], vh[4*kc+3]);
            ((uint4*)(smem + SM_ALO))[kc*128 + tid] =
                make_uint4(vl[4*kc], vl[4*kc+1], vl[4*kc+2], vl[4*kc+3]);
        }
        __syncwarp();

        // ---- MMA: D[32rows x 128] = (Ahi+Alo) * B, fp16 2-pass ----
        #pragma unroll
        for (int chunk = 0; chunk < 4; chunk++) {
            uint afh[2][5][4], afl[2][5][4];
            #pragma unroll
            for (int mt = 0; mt < 2; mt++)
                #pragma unroll
                for (int kt = 0; kt < 5; kt++) {
                    LDSM4(afh[mt][kt][0], afh[mt][kt][1], afh[mt][kt][2], afh[mt][kt][3],
                          aHiB + mt*256 + kt*4096);
                    LDSM4(afl[mt][kt][0], afl[mt][kt][1], afl[mt][kt][2], afl[mt][kt][3],
                          aLoB + mt*256 + kt*4096);
                }
            #pragma unroll
            for (int nt = 0; nt < 4; nt++) {
                uint bf[5][2];
                #pragma unroll
                for (int kt = 0; kt < 5; kt++)
                    LDSM2(bf[kt][0], bf[kt][1], bBase + chunk*512 + nt*128 + kt*4096);

                float d0[4] = {0.f, 0.f, 0.f, 0.f};
                float d1[4] = {0.f, 0.f, 0.f, 0.f};
                #pragma unroll
                for (int kt = 0; kt < 5; kt++) {
                    MMA16816(d0, afh[0][kt], bf[kt]);
                    MMA16816(d1, afh[1][kt], bf[kt]);
                }
                #pragma unroll
                for (int kt = 0; kt < 5; kt++) {
                    MMA16816(d0, afl[0][kt], bf[kt]);
                    MMA16816(d1, afl[1][kt], bf[kt]);
                }

                // ---- epilogue: pair lanes, gates -> c,h ----
                #pragma unroll
                for (int mt = 0; mt < 2; mt++) {
                    float* d = mt ? d1 : d0;
                    const float rx0 = __shfl_xor_sync(0xffffffffu, d[0], 1);
                    const float rx1 = __shfl_xor_sync(0xffffffffu, d[1], 1);
                    const float rx2 = __shfl_xor_sync(0xffffffffu, d[2], 1);
                    const float rx3 = __shfl_xor_sync(0xffffffffu, d[3], 1);
                    const bool odd = lane & 1;
                    const float zi = odd ? rx2 : d[0];
                    const float zf = odd ? rx3 : d[1];
                    const float zg = odd ? d[2] : rx0;
                    const float zo = odd ? d[3] : rx1;
                    const int cidx = (chunk<<3) + (nt<<1) + mt;
                    const float cn = fmaf(fsigmoid(zf), cst[cidx], fsigmoid(zi)*ftanh_(zg));
                    cst[cidx] = cn;
                    const float hvv = fsigmoid(zo) * ftanh_(cn);
                    const int row = (w<<5) + (mt<<4) + (lane>>2) + ((lane&1)<<3);
                    const int jj  = (chunk<<3) + (nt<<1) + ((lane>>1)&1);
                    hbuf[row*33 + jj] = hvv;
                }
            }
        }
        __syncwarp();

        // ---- per-thread: gather h, pred, pack h into A for next step ----
        float pred = boutv;
        uint hh[16], hl[16];
        #pragma unroll
        for (int p = 0; p < 16; p++) {
            const float h0 = hbuf[tid*33 + 2*p];
            const float h1 = hbuf[tid*33 + 2*p + 1];
            pred = fmaf(sW[2*p],   h0, pred);
            pred = fmaf(sW[2*p+1], h1, pred);
            packpair(h0, h1, hh[p], hl[p]);
        }
        #pragma unroll
        for (int kc = 0; kc < 4; kc++) {
            ((uint4*)(smem + SM_AHI))[(6+kc)*128 + tid] =
                make_uint4(hh[4*kc], hh[4*kc+1], hh[4*kc+2], hh[4*kc+3]);
            ((uint4*)(smem + SM_ALO))[(6+kc)*128 + tid] =
                make_uint4(hl[4*kc], hl[4*kc+1], hl[4*kc+2], hl[4*kc+3]);
        }

        optr[(size_t)s*NC] = pred;
        #pragma unroll
        for (int t = 0; t < NHIST-1; t++) xn[t] = xn[t+1];
        xn[NHIST-1] = pred;
        __syncwarp();
    }
}

// ---------------- launch --------------------------------------------------------
extern "C" void kernel_launch(void* const* d_in, const int* in_sizes, int n_in,
                              void* d_out, int out_size)
{
    const float* pm25    = (const float*)d_in[0];
    const float* feature = (const float*)d_in[1];
    // d_in[2] time_feature: unused
    const float* Win  = (const float*)d_in[3];
    const float* bin  = (const float*)d_in[4];
    const float* Wih  = (const float*)d_in[5];
    const float* Whh  = (const float*)d_in[6];
    const float* bih  = (const float*)d_in[7];
    const float* bhh  = (const float*)d_in[8];
    const float* Wout = (const float*)d_in[9];
    const float* bout = (const float*)d_in[10];
    float* out = (float*)d_out;

    cudaFuncSetAttribute(lstm_hmma_kernel,
                         cudaFuncAttributeMaxDynamicSharedMemorySize, SM_SIZE);

    prep1<<<21, 256>>>(Win, bin, Wih, bih, bhh, Wout, bout);
    prep2<<<40, 256>>>(Whh);
    lstm_hmma_kernel<<<GRID, 128, SM_SIZE>>>(pm25, feature, out);
}

// round 8
// speedup vs baseline: 7.9706x; 1.2609x over previous
#include <cuda_runtime.h>
#include <cuda_fp16.h>
#include <cstdint>

typedef unsigned int uint;

#define NC 184
#define NHIST 24
#define NPRED 24
#define NF 17
#define NHID 32
#define NROWS 94208
#define SEQ 48
#define GRID 736
#define NGATE 128

// dynamic smem layout (bytes)
#define SM_BHI  0        // B fp16 tile: [kc][n] 16B rows, 10*2048
#define SM_AHI  20480    // A hi: [kc][row] 16B rows
#define SM_ALO  40960    // A lo
#define SM_HBUF 61440    // h fp32 [128][33]
#define SM_WOUT 78336
#define SM_BOUT 78464
#define SM_SIZE 78592

// ---------------- device-global staged weights --------------------------------
__device__ __half g_B[10240];        // fused B tile, fp16, ldmatrix layout
__device__ float  g_Wf[NGATE*41];    // Wih@Win, n-ordered (n = 4j+g)
__device__ float  g_BG[NGATE];       // fused bias
__device__ float  g_WOUT[NHID];
__device__ float  g_BOUT[1];

__global__ void prep1(const float* __restrict__ Win, const float* __restrict__ bin,
                      const float* __restrict__ Wih, const float* __restrict__ bih,
                      const float* __restrict__ bhh,
                      const float* __restrict__ Wout, const float* __restrict__ bout)
{
    int idx = blockIdx.x*blockDim.x + threadIdx.x;
    if (idx < NGATE*41) {
        int n = idx / 41, k = idx % 41;
        int j = n >> 2, g = n & 3;
        int row = g*NHID + j;
        float s = 0.f;
        #pragma unroll 8
        for (int m = 0; m < NHID; m++) s += Wih[row*NHID + m] * Win[m*41 + k];
        g_Wf[idx] = s;
    }
    if (idx < NGATE) {
        int j = idx >> 2, g = idx & 3;
        int row = g*NHID + j;
        float s = bih[row] + bhh[row];
        #pragma unroll 8
        for (int m = 0; m < NHID; m++) s += Wih[row*NHID + m] * bin[m];
        g_BG[idx] = s;
    }
    if (idx < NHID) g_WOUT[idx] = Wout[idx];
    if (idx == 0) g_BOUT[0] = bout[0];
}

// B[k][n]: k<41 fused W; k=41 bias; 42..47 zero; 48..79 Whh. Stored [kc][n][k%8] fp16.
__global__ void prep2(const float* __restrict__ Whh)
{
    int idx = blockIdx.x*blockDim.x + threadIdx.x;
    if (idx >= NGATE*80) return;
    int n = idx / 80, k = idx % 80;
    int j = n >> 2, g = n & 3;
    float v = 0.f;
    if (k < 41)       v = g_Wf[n*41 + k];
    else if (k == 41) v = g_BG[n];
    else if (k >= 48) v = Whh[(g*NHID + j)*NHID + (k - 48)];
    g_B[(k >> 3)*1024 + n*8 + (k & 7)] = __float2half_rn(v);
}

// ---------------- PTX helpers ---------------------------------------------------
__device__ __forceinline__ uint smem_u32(const void* p) {
    uint a; asm("{ .reg .u64 t; cvta.to.shared.u64 t, %1; cvt.u32.u64 %0, t; }"
                : "=r"(a) : "l"(p));
    return a;
}

#define LDSM4(r0, r1, r2, r3, addr) \
    asm volatile("ldmatrix.sync.aligned.m8n8.x4.shared.b16 {%0,%1,%2,%3}, [%4];" \
        : "=r"(r0), "=r"(r1), "=r"(r2), "=r"(r3) : "r"(addr))

#define LDSM2(r0, r1, addr) \
    asm volatile("ldmatrix.sync.aligned.m8n8.x2.shared.b16 {%0,%1}, [%2];" \
        : "=r"(r0), "=r"(r1) : "r"(addr))

#define MMA16816(d, a, b) \
    asm volatile("mma.sync.aligned.m16n8k16.row.col.f32.f16.f16.f32 " \
        "{%0,%1,%2,%3}, {%4,%5,%6,%7}, {%8,%9}, {%0,%1,%2,%3};" \
        : "+f"((d)[0]), "+f"((d)[1]), "+f"((d)[2]), "+f"((d)[3]) \
        : "r"((a)[0]), "r"((a)[1]), "r"((a)[2]), "r"((a)[3]), \
          "r"((b)[0]), "r"((b)[1]))

// fp32 pair -> fp16x2 hi + fp16x2 lo (a in low half)
__device__ __forceinline__ void packpair(float a, float b, uint& hi, uint& lo) {
    __half2 h2 = __floats2half2_rn(a, b);
    hi = *reinterpret_cast<uint*>(&h2);
    float2 r = __half22float2(h2);
    __half2 l2 = __floats2half2_rn(a - r.x, b - r.y);
    lo = *reinterpret_cast<uint*>(&l2);
}

// MUFU.TANH-based activations: 1 MUFU each
__device__ __forceinline__ float ftanh_(float v) {
    float y; asm("tanh.approx.f32 %0, %1;" : "=f"(y) : "f"(v));
    return y;
}
__device__ __forceinline__ float fsigmoid(float v) {
    float y; asm("tanh.approx.f32 %0, %1;" : "=f"(y) : "f"(v*0.5f));
    return fmaf(0.5f, y, 0.5f);
}

// ---------------- main kernel: HMMA LSTM ---------------------------------------
__global__ void __launch_bounds__(128) lstm_hmma_kernel(
    const float* __restrict__ pm25,
    const float* __restrict__ feature,
    float* __restrict__ out)
{
    extern __shared__ char smem[];
    const uint sb = smem_u32(smem);
    const int tid = threadIdx.x;
    const int w = tid >> 5, lane = tid & 31;

    // stage B + vectors
    {
        const uint4* s = (const uint4*)g_B;
        uint4* d = (uint4*)(smem + SM_BHI);
        #pragma unroll
        for (int i = 0; i < 10; i++) d[i*128 + tid] = s[i*128 + tid];
    }
    if (tid < NHID) ((float*)(smem + SM_WOUT))[tid] = g_WOUT[tid];
    if (tid == 0)   *(float*)(smem + SM_BOUT) = g_BOUT[0];
    {
        uint4 z = make_uint4(0,0,0,0);
        #pragma unroll
        for (int kc = 6; kc < 10; kc++) {
            ((uint4*)(smem + SM_AHI))[kc*128 + tid] = z;   // h=0
            ((uint4*)(smem + SM_ALO))[kc*128 + tid] = z;
        }
    }
    __syncthreads();

    // per-thread row state
    const int r = blockIdx.x*128 + tid;
    const int b = r / NC;
    const int c = r - b*NC;

    float xn[NHIST];
    #pragma unroll
    for (int t = 0; t < NHIST; t++) xn[t] = pm25[(size_t)r*NHIST + t];
    float cst[32];
    #pragma unroll
    for (int i = 0; i < 32; i++) cst[i] = 0.0f;

    const float* fptr = feature + (((size_t)b*SEQ + NHIST)*NC + c)*NF;
    float* optr = out + ((size_t)b*NPRED)*NC + c;

    const float* sW  = (const float*)(smem + SM_WOUT);
    const float boutv = *(const float*)(smem + SM_BOUT);
    float* hbuf = (float*)(smem + SM_HBUF);

    // ldmatrix lane base addresses
    const uint rowA   = (uint)(w<<5) + (lane & 7) + (((lane >> 3) & 1) << 3);
    const uint aHiB   = sb + SM_AHI + rowA*16 + ((uint)(lane >> 4) & 1)*2048;
    const uint aLoB   = sb + SM_ALO + rowA*16 + ((uint)(lane >> 4) & 1)*2048;
    const uint bBase  = sb + SM_BHI + (uint)(lane & 7)*16 + (((uint)(lane >> 3) & 1))*2048;

    #pragma unroll 1
    for (int s = 0; s < NPRED; s++) {
        // ---- build v = [xn | feat | 1(bias) | 0pad], split fp16 hi/lo ----
        float ft[NF];
        #pragma unroll
        for (int f = 0; f < NF; f++) ft[f] = fptr[f];
        fptr += (size_t)NC*NF;

        uint vh[24], vl[24];
        #pragma unroll
        for (int p = 0; p < 12; p++) packpair(xn[2*p], xn[2*p+1], vh[p], vl[p]);
        #pragma unroll
        for (int p = 0; p < 8; p++) packpair(ft[2*p], ft[2*p+1], vh[12+p], vl[12+p]);
        packpair(ft[16], 1.0f, vh[20], vl[20]);        // k40 = feat16, k41 = 1.0 (bias col)
        vh[21] = vh[22] = vh[23] = 0u;
        vl[21] = vl[22] = vl[23] = 0u;

        #pragma unroll
        for (int kc = 0; kc < 6; kc++) {
            ((uint4*)(smem + SM_AHI))[kc*128 + tid] =
                make_uint4(vh[4*kc], vh[4*kc+1], vh[4*kc+2], vh[4*kc+3]);
            ((uint4*)(smem + SM_ALO))[kc*128 + tid] =
                make_uint4(vl[4*kc], vl[4*kc+1], vl[4*kc+2], vl[4*kc+3]);
        }
        __syncwarp();

        // ---- hoisted A fragment loads (shared across all 4 N-chunks) ----
        uint afh[2][5][4], afl[2][5][4];
        #pragma unroll
        for (int mt = 0; mt < 2; mt++)
            #pragma unroll
            for (int kt = 0; kt < 5; kt++) {
                LDSM4(afh[mt][kt][0], afh[mt][kt][1], afh[mt][kt][2], afh[mt][kt][3],
                      aHiB + mt*256 + kt*4096);
                LDSM4(afl[mt][kt][0], afl[mt][kt][1], afl[mt][kt][2], afl[mt][kt][3],
                      aLoB + mt*256 + kt*4096);
            }

        // ---- MMA: D[32rows x 128] = (Ahi+Alo) * B, fp16 2-pass ----
        #pragma unroll
        for (int chunk = 0; chunk < 4; chunk++) {
            #pragma unroll
            for (int nt = 0; nt < 4; nt++) {
                uint bf[5][2];
                #pragma unroll
                for (int kt = 0; kt < 5; kt++)
                    LDSM2(bf[kt][0], bf[kt][1], bBase + chunk*512 + nt*128 + kt*4096);

                float d0[4] = {0.f, 0.f, 0.f, 0.f};
                float d1[4] = {0.f, 0.f, 0.f, 0.f};
                #pragma unroll
                for (int kt = 0; kt < 5; kt++) {
                    MMA16816(d0, afh[0][kt], bf[kt]);
                    MMA16816(d1, afh[1][kt], bf[kt]);
                }
                #pragma unroll
                for (int kt = 0; kt < 5; kt++) {
                    MMA16816(d0, afl[0][kt], bf[kt]);
                    MMA16816(d1, afl[1][kt], bf[kt]);
                }

                // ---- epilogue: pair lanes, gates -> c,h ----
                #pragma unroll
                for (int mt = 0; mt < 2; mt++) {
                    float* d = mt ? d1 : d0;
                    const float rx0 = __shfl_xor_sync(0xffffffffu, d[0], 1);
                    const float rx1 = __shfl_xor_sync(0xffffffffu, d[1], 1);
                    const float rx2 = __shfl_xor_sync(0xffffffffu, d[2], 1);
                    const float rx3 = __shfl_xor_sync(0xffffffffu, d[3], 1);
                    const bool odd = lane & 1;
                    const float zi = odd ? rx2 : d[0];
                    const float zf = odd ? rx3 : d[1];
                    const float zg = odd ? d[2] : rx0;
                    const float zo = odd ? d[3] : rx1;
                    const int cidx = (chunk<<3) + (nt<<1) + mt;
                    const float cn = fmaf(fsigmoid(zf), cst[cidx], fsigmoid(zi)*ftanh_(zg));
                    cst[cidx] = cn;
                    const float hvv = fsigmoid(zo) * ftanh_(cn);
                    const int row = (w<<5) + (mt<<4) + (lane>>2) + ((lane&1)<<3);
                    const int jj  = (chunk<<3) + (nt<<1) + ((lane>>1)&1);
                    hbuf[row*33 + jj] = hvv;
                }
            }
        }
        __syncwarp();

        // ---- per-thread: gather h, pred, pack h into A for next step ----
        float pred = boutv;
        uint hh[16], hl[16];
        #pragma unroll
        for (int p = 0; p < 16; p++) {
            const float h0 = hbuf[tid*33 + 2*p];
            const float h1 = hbuf[tid*33 + 2*p + 1];
            pred = fmaf(sW[2*p],   h0, pred);
            pred = fmaf(sW[2*p+1], h1, pred);
            packpair(h0, h1, hh[p], hl[p]);
        }
        #pragma unroll
        for (int kc = 0; kc < 4; kc++) {
            ((uint4*)(smem + SM_AHI))[(6+kc)*128 + tid] =
                make_uint4(hh[4*kc], hh[4*kc+1], hh[4*kc+2], hh[4*kc+3]);
            ((uint4*)(smem + SM_ALO))[(6+kc)*128 + tid] =
                make_uint4(hl[4*kc], hl[4*kc+1], hl[4*kc+2], hl[4*kc+3]);
        }

        optr[(size_t)s*NC] = pred;
        #pragma unroll
        for (int t = 0; t < NHIST-1; t++) xn[t] = xn[t+1];
        xn[NHIST-1] = pred;
        __syncwarp();
    }
}

// ---------------- launch --------------------------------------------------------
extern "C" void kernel_launch(void* const* d_in, const int* in_sizes, int n_in,
                              void* d_out, int out_size)
{
    const float* pm25    = (const float*)d_in[0];
    const float* feature = (const float*)d_in[1];
    // d_in[2] time_feature: unused
    const float* Win  = (const float*)d_in[3];
    const float* bin  = (const float*)d_in[4];
    const float* Wih  = (const float*)d_in[5];
    const float* Whh  = (const float*)d_in[6];
    const float* bih  = (const float*)d_in[7];
    const float* bhh  = (const float*)d_in[8];
    const float* Wout = (const float*)d_in[9];
    const float* bout = (const float*)d_in[10];
    float* out = (float*)d_out;

    cudaFuncSetAttribute(lstm_hmma_kernel,
                         cudaFuncAttributeMaxDynamicSharedMemorySize, SM_SIZE);

    prep1<<<21, 256>>>(Win, bin, Wih, bih, bhh, Wout, bout);
    prep2<<<40, 256>>>(Whh);
    lstm_hmma_kernel<<<GRID, 128, SM_SIZE>>>(pm25, feature, out);
}

// round 10
// speedup vs baseline: 9.8598x; 1.2370x over previous
#include <cuda_runtime.h>
#include <cuda_fp16.h>
#include <cstdint>

typedef unsigned int uint;

#define NC 184
#define NHIST 24
#define NPRED 24
#define NF 17
#define NHID 32
#define NROWS 94208
#define SEQ 48
#define GRID 736
#define NGATE 128

// dynamic smem layout (bytes)
#define SM_BHI  0        // B fp16 tile: [kc][n] 16B rows, 10*2048
#define SM_AHI  20480    // A hi: [kc][row] 16B rows
#define SM_ALO  40960    // A lo
#define SM_HBUF 61440    // h fp32 [128][33]
#define SM_WOUT 78336
#define SM_BOUT 78464
#define SM_SIZE 78592

// ---------------- device-global staged weights --------------------------------
__device__ __half g_B[10240];        // fused B tile, fp16, ldmatrix layout, n = g*32+j
__device__ float  g_Wf[NGATE*41];    // fused Wih@Win, row-direct (row = g*32+j)
__device__ float  g_BG[NGATE];       // fused bias, row-direct
__device__ float  g_WOUT[NHID];
__device__ float  g_BOUT[1];

__global__ void prep1(const float* __restrict__ Win, const float* __restrict__ bin,
                      const float* __restrict__ Wih, const float* __restrict__ bih,
                      const float* __restrict__ bhh,
                      const float* __restrict__ Wout, const float* __restrict__ bout)
{
    int idx = blockIdx.x*blockDim.x + threadIdx.x;
    if (idx < NGATE*41) {
        int row = idx / 41, k = idx % 41;
        float s = 0.f;
        #pragma unroll 8
        for (int m = 0; m < NHID; m++) s += Wih[row*NHID + m] * Win[m*41 + k];
        g_Wf[idx] = s;
    }
    if (idx < NGATE) {
        float s = bih[idx] + bhh[idx];
        #pragma unroll 8
        for (int m = 0; m < NHID; m++) s += Wih[idx*NHID + m] * bin[m];
        g_BG[idx] = s;
    }
    if (idx < NHID) g_WOUT[idx] = Wout[idx];
    if (idx == 0) g_BOUT[0] = bout[0];
}

// B[k][n], n = g*32+j (gate-planar): k<41 fused W; k=41 bias; 42..47 zero; 48..79 Whh.
// Stored [k>>3][n][k&7] fp16 (16B per (kc,n) row for ldmatrix).
__global__ void prep2(const float* __restrict__ Whh)
{
    int idx = blockIdx.x*blockDim.x + threadIdx.x;
    if (idx >= NGATE*80) return;
    int n = idx / 80, k = idx % 80;
    float v = 0.f;
    if (k < 41)       v = g_Wf[n*41 + k];
    else if (k == 41) v = g_BG[n];
    else if (k >= 48) v = Whh[n*NHID + (k - 48)];
    g_B[(k >> 3)*1024 + n*8 + (k & 7)] = __float2half_rn(v);
}

// ---------------- PTX helpers ---------------------------------------------------
__device__ __forceinline__ uint smem_u32(const void* p) {
    uint a; asm("{ .reg .u64 t; cvta.to.shared.u64 t, %1; cvt.u32.u64 %0, t; }"
                : "=r"(a) : "l"(p));
    return a;
}

#define LDSM4(r0, r1, r2, r3, addr) \
    asm volatile("ldmatrix.sync.aligned.m8n8.x4.shared.b16 {%0,%1,%2,%3}, [%4];" \
        : "=r"(r0), "=r"(r1), "=r"(r2), "=r"(r3) : "r"(addr))

#define LDSM2(r0, r1, addr) \
    asm volatile("ldmatrix.sync.aligned.m8n8.x2.shared.b16 {%0,%1}, [%2];" \
        : "=r"(r0), "=r"(r1) : "r"(addr))

#define MMA16816(d, a, b) \
    asm volatile("mma.sync.aligned.m16n8k16.row.col.f32.f16.f16.f32 " \
        "{%0,%1,%2,%3}, {%4,%5,%6,%7}, {%8,%9}, {%0,%1,%2,%3};" \
        : "+f"((d)[0]), "+f"((d)[1]), "+f"((d)[2]), "+f"((d)[3]) \
        : "r"((a)[0]), "r"((a)[1]), "r"((a)[2]), "r"((a)[3]), \
          "r"((b)[0]), "r"((b)[1]))

// fp32 pair -> fp16x2 hi + fp16x2 lo (a in low half)
__device__ __forceinline__ void packpair(float a, float b, uint& hi, uint& lo) {
    __half2 h2 = __floats2half2_rn(a, b);
    hi = *reinterpret_cast<uint*>(&h2);
    float2 r = __half22float2(h2);
    __half2 l2 = __floats2half2_rn(a - r.x, b - r.y);
    lo = *reinterpret_cast<uint*>(&l2);
}

// MUFU.TANH-based activations: 1 MUFU each
__device__ __forceinline__ float ftanh_(float v) {
    float y; asm("tanh.approx.f32 %0, %1;" : "=f"(y) : "f"(v));
    return y;
}
__device__ __forceinline__ float fsigmoid(float v) {
    float y; asm("tanh.approx.f32 %0, %1;" : "=f"(y) : "f"(v*0.5f));
    return fmaf(0.5f, y, 0.5f);
}

// ---------------- main kernel: HMMA LSTM, shuffle-free epilogue -----------------
__global__ void __launch_bounds__(128) lstm_hmma_kernel(
    const float* __restrict__ pm25,
    const float* __restrict__ feature,
    float* __restrict__ out)
{
    extern __shared__ char smem[];
    const uint sb = smem_u32(smem);
    const int tid = threadIdx.x;
    const int w = tid >> 5, lane = tid & 31;

    // stage B + vectors
    {
        const uint4* s = (const uint4*)g_B;
        uint4* d = (uint4*)(smem + SM_BHI);
        #pragma unroll
        for (int i = 0; i < 10; i++) d[i*128 + tid] = s[i*128 + tid];
    }
    if (tid < NHID) ((float*)(smem + SM_WOUT))[tid] = g_WOUT[tid];
    if (tid == 0)   *(float*)(smem + SM_BOUT) = g_BOUT[0];
    {
        uint4 z = make_uint4(0,0,0,0);
        #pragma unroll
        for (int kc = 6; kc < 10; kc++) {
            ((uint4*)(smem + SM_AHI))[kc*128 + tid] = z;   // h=0
            ((uint4*)(smem + SM_ALO))[kc*128 + tid] = z;
        }
    }
    __syncthreads();

    // per-thread row state (thread = row for I/O, A-pack, pred)
    const int r = blockIdx.x*128 + tid;
    const int b = r / NC;
    const int c = r - b*NC;

    float xn[NHIST];
    #pragma unroll
    for (int t = 0; t < NHIST; t++) xn[t] = pm25[(size_t)r*NHIST + t];
    // c-state: cell (row', j) owned by the thread whose d-regs produce it
    float cst[32];
    #pragma unroll
    for (int i = 0; i < 32; i++) cst[i] = 0.0f;

    const float* fptr = feature + (((size_t)b*SEQ + NHIST)*NC + c)*NF;
    float* optr = out + ((size_t)b*NPRED)*NC + c;

    const float* sW  = (const float*)(smem + SM_WOUT);
    const float boutv = *(const float*)(smem + SM_BOUT);
    float* hbuf = (float*)(smem + SM_HBUF);

    // ldmatrix lane base addresses
    const uint rowA   = (uint)(w<<5) + (lane & 7) + (((lane >> 3) & 1) << 3);
    const uint aHiB   = sb + SM_AHI + rowA*16 + ((uint)(lane >> 4) & 1)*2048;
    const uint aLoB   = sb + SM_ALO + rowA*16 + ((uint)(lane >> 4) & 1)*2048;
    const uint bBase  = sb + SM_BHI + (uint)(lane & 7)*16 + (((uint)(lane >> 3) & 1))*2048;

    // epilogue cell coordinates for this lane
    const int q = lane & 3;
    const int rbase = (w<<5) + (lane>>2);   // + mt*16 + rh*8

    #pragma unroll 1
    for (int s = 0; s < NPRED; s++) {
        // ---- build v = [xn | feat | 1(bias) | 0pad], split fp16 hi/lo ----
        float ft[NF];
        #pragma unroll
        for (int f = 0; f < NF; f++) ft[f] = fptr[f];
        fptr += (size_t)NC*NF;

        uint vh[24], vl[24];
        #pragma unroll
        for (int p = 0; p < 12; p++) packpair(xn[2*p], xn[2*p+1], vh[p], vl[p]);
        #pragma unroll
        for (int p = 0; p < 8; p++) packpair(ft[2*p], ft[2*p+1], vh[12+p], vl[12+p]);
        packpair(ft[16], 1.0f, vh[20], vl[20]);        // k40 = feat16, k41 = 1.0 (bias col)
        vh[21] = vh[22] = vh[23] = 0u;
        vl[21] = vl[22] = vl[23] = 0u;

        #pragma unroll
        for (int kc = 0; kc < 6; kc++) {
            ((uint4*)(smem + SM_AHI))[kc*128 + tid] =
                make_uint4(vh[4*kc], vh[4*kc+1], vh[4*kc+2], vh[4*kc+3]);
            ((uint4*)(smem + SM_ALO))[kc*128 + tid] =
                make_uint4(vl[4*kc], vl[4*kc+1], vl[4*kc+2], vl[4*kc+3]);
        }
        __syncwarp();

        // ---- hoisted A fragment loads (shared across all 16 n-tiles) ----
        uint afh[2][5][4], afl[2][5][4];
        #pragma unroll
        for (int mt = 0; mt < 2; mt++)
            #pragma unroll
            for (int kt = 0; kt < 5; kt++) {
                LDSM4(afh[mt][kt][0], afh[mt][kt][1], afh[mt][kt][2], afh[mt][kt][3],
                      aHiB + mt*256 + kt*4096);
                LDSM4(afl[mt][kt][0], afl[mt][kt][1], afl[mt][kt][2], afl[mt][kt][3],
                      aLoB + mt*256 + kt*4096);
            }

        // ---- per n-tile: 4 gate-planes accumulate, then shuffle-free epilogue ----
        #pragma unroll
        for (int nt = 0; nt < 4; nt++) {
            float d[4][2][4];
            #pragma unroll
            for (int g = 0; g < 4; g++) {
                #pragma unroll
                for (int mt = 0; mt < 2; mt++)
                    #pragma unroll
                    for (int i = 0; i < 4; i++) d[g][mt][i] = 0.f;
                #pragma unroll
                for (int kt = 0; kt < 5; kt++) {
                    uint bf[2];
                    LDSM2(bf[0], bf[1], bBase + g*512 + nt*128 + kt*4096);
                    MMA16816(d[g][0], afh[0][kt], bf);
                    MMA16816(d[g][1], afh[1][kt], bf);
                    MMA16816(d[g][0], afl[0][kt], bf);
                    MMA16816(d[g][1], afl[1][kt], bf);
                }
            }
            // cells: rows rbase + mt*16 + rh*8 ; j = nt*8 + 2q + t
            #pragma unroll
            for (int mt = 0; mt < 2; mt++)
                #pragma unroll
                for (int rh = 0; rh < 2; rh++)
                    #pragma unroll
                    for (int t = 0; t < 2; t++) {
                        const int dreg = 2*rh + t;
                        const float zi = d[0][mt][dreg];
                        const float zf = d[1][mt][dreg];
                        const float zg = d[2][mt][dreg];
                        const float zo = d[3][mt][dreg];
                        const int ci = ((nt*2 + mt)*2 + rh)*2 + t;
                        const float cn = fmaf(fsigmoid(zf), cst[ci],
                                              fsigmoid(zi)*ftanh_(zg));
                        cst[ci] = cn;
                        const float hvv = fsigmoid(zo) * ftanh_(cn);
                        const int row = rbase + (mt<<4) + (rh<<3);
                        const int jj  = (nt<<3) + (q<<1) + t;
                        hbuf[row*33 + jj] = hvv;
                    }
        }
        __syncwarp();

        // ---- per-thread: gather own row's h, pred, pack h into A for next step ----
        float pred = boutv;
        uint hh[16], hl[16];
        #pragma unroll
        for (int p = 0; p < 16; p++) {
            const float h0 = hbuf[tid*33 + 2*p];
            const float h1 = hbuf[tid*33 + 2*p + 1];
            pred = fmaf(sW[2*p],   h0, pred);
            pred = fmaf(sW[2*p+1], h1, pred);
            packpair(h0, h1, hh[p], hl[p]);
        }
        #pragma unroll
        for (int kc = 0; kc < 4; kc++) {
            ((uint4*)(smem + SM_AHI))[(6+kc)*128 + tid] =
                make_uint4(hh[4*kc], hh[4*kc+1], hh[4*kc+2], hh[4*kc+3]);
            ((uint4*)(smem + SM_ALO))[(6+kc)*128 + tid] =
                make_uint4(hl[4*kc], hl[4*kc+1], hl[4*kc+2], hl[4*kc+3]);
        }

        optr[(size_t)s*NC] = pred;
        #pragma unroll
        for (int t = 0; t < NHIST-1; t++) xn[t] = xn[t+1];
        xn[NHIST-1] = pred;
        __syncwarp();
    }
}

// ---------------- launch --------------------------------------------------------
extern "C" void kernel_launch(void* const* d_in, const int* in_sizes, int n_in,
                              void* d_out, int out_size)
{
    const float* pm25    = (const float*)d_in[0];
    const float* feature = (const float*)d_in[1];
    // d_in[2] time_feature: unused
    const float* Win  = (const float*)d_in[3];
    const float* bin  = (const float*)d_in[4];
    const float* Wih  = (const float*)d_in[5];
    const float* Whh  = (const float*)d_in[6];
    const float* bih  = (const float*)d_in[7];
    const float* bhh  = (const float*)d_in[8];
    const float* Wout = (const float*)d_in[9];
    const float* bout = (const float*)d_in[10];
    float* out = (float*)d_out;

    cudaFuncSetAttribute(lstm_hmma_kernel,
                         cudaFuncAttributeMaxDynamicSharedMemorySize, SM_SIZE);

    prep1<<<21, 256>>>(Win, bin, Wih, bih, bhh, Wout, bout);
    prep2<<<40, 256>>>(Whh);
    lstm_hmma_kernel<<<GRID, 128, SM_SIZE>>>(pm25, feature, out);
}

// round 11
// speedup vs baseline: 15.8128x; 1.6038x over previous
#include <cuda_runtime.h>
#include <cuda_fp16.h>
#include <cstdint>

typedef unsigned int uint;

#define NC 184
#define NHIST 24
#define NPRED 24
#define NF 17
#define NHID 32
#define NROWS 94208
#define SEQ 48
#define GRID 736
#define NGATE 128

// dynamic smem layout (bytes)
#define SM_BHI  0        // B fp16 tile: [kc][n] 16B rows, 10*2048
#define SM_AHI  20480    // A fp16: [kc][row] 16B rows, 10*2048
#define SM_HBUF 40960    // h fp32 [128][33]
#define SM_WOUT 57856
#define SM_BOUT 57984
#define SM_SIZE 58112

// ---------------- device-global staged weights --------------------------------
__device__ __half g_B[10240];        // fused B tile, fp16, ldmatrix layout, n = g*32+j
__device__ float  g_Wf[NGATE*41];    // fused Wih@Win, row-direct (row = g*32+j)
__device__ float  g_BG[NGATE];       // fused bias, row-direct
__device__ float  g_WOUT[NHID];
__device__ float  g_BOUT[1];

__global__ void prep1(const float* __restrict__ Win, const float* __restrict__ bin,
                      const float* __restrict__ Wih, const float* __restrict__ bih,
                      const float* __restrict__ bhh,
                      const float* __restrict__ Wout, const float* __restrict__ bout)
{
    int idx = blockIdx.x*blockDim.x + threadIdx.x;
    if (idx < NGATE*41) {
        int row = idx / 41, k = idx % 41;
        float s = 0.f;
        #pragma unroll 8
        for (int m = 0; m < NHID; m++) s += Wih[row*NHID + m] * Win[m*41 + k];
        g_Wf[idx] = s;
    }
    if (idx < NGATE) {
        float s = bih[idx] + bhh[idx];
        #pragma unroll 8
        for (int m = 0; m < NHID; m++) s += Wih[idx*NHID + m] * bin[m];
        g_BG[idx] = s;
    }
    if (idx < NHID) g_WOUT[idx] = Wout[idx];
    if (idx == 0) g_BOUT[0] = bout[0];
}

// B[k][n], n = g*32+j (gate-planar): k<41 fused W; k=41 bias; 42..47 zero; 48..79 Whh.
// Stored [k>>3][n][k&7] fp16 (16B per (kc,n) row for ldmatrix).
__global__ void prep2(const float* __restrict__ Whh)
{
    int idx = blockIdx.x*blockDim.x + threadIdx.x;
    if (idx >= NGATE*80) return;
    int n = idx / 80, k = idx % 80;
    float v = 0.f;
    if (k < 41)       v = g_Wf[n*41 + k];
    else if (k == 41) v = g_BG[n];
    else if (k >= 48) v = Whh[n*NHID + (k - 48)];
    g_B[(k >> 3)*1024 + n*8 + (k & 7)] = __float2half_rn(v);
}

// ---------------- PTX helpers ---------------------------------------------------
__device__ __forceinline__ uint smem_u32(const void* p) {
    uint a; asm("{ .reg .u64 t; cvta.to.shared.u64 t, %1; cvt.u32.u64 %0, t; }"
                : "=r"(a) : "l"(p));
    return a;
}

#define LDSM4(r0, r1, r2, r3, addr) \
    asm volatile("ldmatrix.sync.aligned.m8n8.x4.shared.b16 {%0,%1,%2,%3}, [%4];" \
        : "=r"(r0), "=r"(r1), "=r"(r2), "=r"(r3) : "r"(addr))

#define LDSM2(r0, r1, addr) \
    asm volatile("ldmatrix.sync.aligned.m8n8.x2.shared.b16 {%0,%1}, [%2];" \
        : "=r"(r0), "=r"(r1) : "r"(addr))

#define MMA16816(d, a, b) \
    asm volatile("mma.sync.aligned.m16n8k16.row.col.f32.f16.f16.f32 " \
        "{%0,%1,%2,%3}, {%4,%5,%6,%7}, {%8,%9}, {%0,%1,%2,%3};" \
        : "+f"((d)[0]), "+f"((d)[1]), "+f"((d)[2]), "+f"((d)[3]) \
        : "r"((a)[0]), "r"((a)[1]), "r"((a)[2]), "r"((a)[3]), \
          "r"((b)[0]), "r"((b)[1]))

// fp32 pair -> fp16x2 (a in low half)
__device__ __forceinline__ uint packh2(float a, float b) {
    __half2 h2 = __floats2half2_rn(a, b);
    return *reinterpret_cast<uint*>(&h2);
}

// MUFU.TANH-based activations: 1 MUFU each
__device__ __forceinline__ float ftanh_(float v) {
    float y; asm("tanh.approx.f32 %0, %1;" : "=f"(y) : "f"(v));
    return y;
}
__device__ __forceinline__ float fsigmoid(float v) {
    float y; asm("tanh.approx.f32 %0, %1;" : "=f"(y) : "f"(v*0.5f));
    return fmaf(0.5f, y, 0.5f);
}

// ---------------- main kernel: HMMA LSTM, single-pass fp16 ----------------------
__global__ void __launch_bounds__(128) lstm_hmma_kernel(
    const float* __restrict__ pm25,
    const float* __restrict__ feature,
    float* __restrict__ out)
{
    extern __shared__ char smem[];
    const uint sb = smem_u32(smem);
    const int tid = threadIdx.x;
    const int w = tid >> 5, lane = tid & 31;

    // stage B + vectors
    {
        const uint4* s = (const uint4*)g_B;
        uint4* d = (uint4*)(smem + SM_BHI);
        #pragma unroll
        for (int i = 0; i < 10; i++) d[i*128 + tid] = s[i*128 + tid];
    }
    if (tid < NHID) ((float*)(smem + SM_WOUT))[tid] = g_WOUT[tid];
    if (tid == 0)   *(float*)(smem + SM_BOUT) = g_BOUT[0];
    {
        uint4 z = make_uint4(0,0,0,0);
        #pragma unroll
        for (int kc = 6; kc < 10; kc++)
            ((uint4*)(smem + SM_AHI))[kc*128 + tid] = z;   // h=0
    }
    __syncthreads();

    // per-thread row state (thread = row for I/O, A-pack, pred)
    const int r = blockIdx.x*128 + tid;
    const int b = r / NC;
    const int c = r - b*NC;

    float xn[NHIST];
    #pragma unroll
    for (int t = 0; t < NHIST; t++) xn[t] = pm25[(size_t)r*NHIST + t];
    // c-state: cell (row', j) owned by the thread whose d-regs produce it
    float cst[32];
    #pragma unroll
    for (int i = 0; i < 32; i++) cst[i] = 0.0f;

    const float* fptr = feature + (((size_t)b*SEQ + NHIST)*NC + c)*NF;
    float* optr = out + ((size_t)b*NPRED)*NC + c;

    const float* sW  = (const float*)(smem + SM_WOUT);
    const float boutv = *(const float*)(smem + SM_BOUT);
    float* hbuf = (float*)(smem + SM_HBUF);

    // ldmatrix lane base addresses
    const uint rowA   = (uint)(w<<5) + (lane & 7) + (((lane >> 3) & 1) << 3);
    const uint aHiB   = sb + SM_AHI + rowA*16 + ((uint)(lane >> 4) & 1)*2048;
    const uint bBase  = sb + SM_BHI + (uint)(lane & 7)*16 + (((uint)(lane >> 3) & 1))*2048;

    // epilogue cell coordinates for this lane
    const int q = lane & 3;
    const int rbase = (w<<5) + (lane>>2);   // + mt*16 + rh*8

    #pragma unroll 1
    for (int s = 0; s < NPRED; s++) {
        // ---- build v = [xn | feat | 1(bias) | 0pad] fp16 ----
        float ft[NF];
        #pragma unroll
        for (int f = 0; f < NF; f++) ft[f] = fptr[f];
        fptr += (size_t)NC*NF;

        uint vh[24];
        #pragma unroll
        for (int p = 0; p < 12; p++) vh[p] = packh2(xn[2*p], xn[2*p+1]);
        #pragma unroll
        for (int p = 0; p < 8; p++) vh[12+p] = packh2(ft[2*p], ft[2*p+1]);
        vh[20] = packh2(ft[16], 1.0f);                // k40 = feat16, k41 = 1.0 (bias col)
        vh[21] = vh[22] = vh[23] = 0u;

        #pragma unroll
        for (int kc = 0; kc < 6; kc++)
            ((uint4*)(smem + SM_AHI))[kc*128 + tid] =
                make_uint4(vh[4*kc], vh[4*kc+1], vh[4*kc+2], vh[4*kc+3]);
        __syncwarp();

        // ---- hoisted A fragment loads (shared across all 16 n-tiles) ----
        uint afh[2][5][4];
        #pragma unroll
        for (int mt = 0; mt < 2; mt++)
            #pragma unroll
            for (int kt = 0; kt < 5; kt++)
                LDSM4(afh[mt][kt][0], afh[mt][kt][1], afh[mt][kt][2], afh[mt][kt][3],
                      aHiB + mt*256 + kt*4096);

        // ---- per n-tile: 4 gate-planes accumulate, then shuffle-free epilogue ----
        #pragma unroll
        for (int nt = 0; nt < 4; nt++) {
            float d[4][2][4];
            #pragma unroll
            for (int g = 0; g < 4; g++) {
                #pragma unroll
                for (int mt = 0; mt < 2; mt++)
                    #pragma unroll
                    for (int i = 0; i < 4; i++) d[g][mt][i] = 0.f;
                #pragma unroll
                for (int kt = 0; kt < 5; kt++) {
                    uint bf[2];
                    LDSM2(bf[0], bf[1], bBase + g*512 + nt*128 + kt*4096);
                    MMA16816(d[g][0], afh[0][kt], bf);
                    MMA16816(d[g][1], afh[1][kt], bf);
                }
            }
            // cells: rows rbase + mt*16 + rh*8 ; j = nt*8 + 2q + t
            #pragma unroll
            for (int mt = 0; mt < 2; mt++)
                #pragma unroll
                for (int rh = 0; rh < 2; rh++)
                    #pragma unroll
                    for (int t = 0; t < 2; t++) {
                        const int dreg = 2*rh + t;
                        const float zi = d[0][mt][dreg];
                        const float zf = d[1][mt][dreg];
                        const float zg = d[2][mt][dreg];
                        const float zo = d[3][mt][dreg];
                        const int ci = ((nt*2 + mt)*2 + rh)*2 + t;
                        const float cn = fmaf(fsigmoid(zf), cst[ci],
                                              fsigmoid(zi)*ftanh_(zg));
                        cst[ci] = cn;
                        const float hvv = fsigmoid(zo) * ftanh_(cn);
                        const int row = rbase + (mt<<4) + (rh<<3);
                        const int jj  = (nt<<3) + (q<<1) + t;
                        hbuf[row*33 + jj] = hvv;
                    }
        }
        __syncwarp();

        // ---- per-thread: gather own row's h, pred, pack h into A for next step ----
        float pred = boutv;
        uint hh[16];
        #pragma unroll
        for (int p = 0; p < 16; p++) {
            const float h0 = hbuf[tid*33 + 2*p];
            const float h1 = hbuf[tid*33 + 2*p + 1];
            pred = fmaf(sW[2*p],   h0, pred);
            pred = fmaf(sW[2*p+1], h1, pred);
            hh[p] = packh2(h0, h1);
        }
        #pragma unroll
        for (int kc = 0; kc < 4; kc++)
            ((uint4*)(smem + SM_AHI))[(6+kc)*128 + tid] =
                make_uint4(hh[4*kc], hh[4*kc+1], hh[4*kc+2], hh[4*kc+3]);

        optr[(size_t)s*NC] = pred;
        #pragma unroll
        for (int t = 0; t < NHIST-1; t++) xn[t] = xn[t+1];
        xn[NHIST-1] = pred;
        __syncwarp();
    }
}

// ---------------- launch --------------------------------------------------------
extern "C" void kernel_launch(void* const* d_in, const int* in_sizes, int n_in,
                              void* d_out, int out_size)
{
    const float* pm25    = (const float*)d_in[0];
    const float* feature = (const float*)d_in[1];
    // d_in[2] time_feature: unused
    const float* Win  = (const float*)d_in[3];
    const float* bin  = (const float*)d_in[4];
    const float* Wih  = (const float*)d_in[5];
    const float* Whh  = (const float*)d_in[6];
    const float* bih  = (const float*)d_in[7];
    const float* bhh  = (const float*)d_in[8];
    const float* Wout = (const float*)d_in[9];
    const float* bout = (const float*)d_in[10];
    float* out = (float*)d_out;

    cudaFuncSetAttribute(lstm_hmma_kernel,
                         cudaFuncAttributeMaxDynamicSharedMemorySize, SM_SIZE);

    prep1<<<21, 256>>>(Win, bin, Wih, bih, bhh, Wout, bout);
    prep2<<<40, 256>>>(Whh);
    lstm_hmma_kernel<<<GRID, 128, SM_SIZE>>>(pm25, feature, out);
}